// round 8
// baseline (speedup 1.0000x reference)
#include <cuda_runtime.h>
#include <cstdint>

typedef unsigned long long ull;

// ---------------- problem constants ----------------
// T=4, B=2, Ck=256, Cv=512, H=W=96, scales {1,2,3,6}, MAX=6, M=144, N=9216

// ---------------- device scratch (static, no allocation) ----------------
__device__ __align__(16) float g_pool6_k[2048 * 36];          // [T*B*Ck][36] block means
__device__ __align__(16) float g_pool6_v[4096 * 36];          // [T*B*Cv][36]
__device__ __align__(16) float g_convk[4 * 2 * 4 * 64 * 36];  // [tb][si][o][pos<=36]
__device__ __align__(16) float g_convv[4 * 2 * 4 * 128 * 36];
// duplicated layouts: every scalar stored twice (f32x2 broadcast operand, no dup movs)
__device__ __align__(16) float g_mkTd[2 * 256 * 288];         // [b][c][2*m] (x Ck^-0.5 folded)
__device__ __align__(16) float g_mvTd[2 * 144 * 1024];        // [b][m][2*v]

__constant__ int c_scale[4] = {1, 2, 3, 6};
// bilinear upsample tables (jax.image.resize bilinear, half-pixel == edge clamp here)
__constant__ int UI0[4][6] = {
    {0,0,0,0,0,0},
    {0,0,0,0,1,1},
    {0,0,0,1,1,2},
    {0,1,2,3,4,5}};
__constant__ int UI1[4][6] = {
    {0,0,0,0,0,0},
    {0,1,1,1,1,1},
    {0,1,1,2,2,2},
    {0,1,2,3,4,5}};
__constant__ float UW[4][6] = {
    {0.f,0.f,0.f,0.f,0.f,0.f},
    {0.f, 1.f/6.f, 0.5f, 5.f/6.f, 0.f, 0.f},
    {0.f, 0.25f, 0.75f, 0.25f, 0.75f, 0.f},
    {0.f,0.f,0.f,0.f,0.f,0.f}};

// ---------------- f32x2 helpers ----------------
__device__ __forceinline__ ull fma2(ull a, ull b, ull c) {
    ull d;
    asm("fma.rn.f32x2 %0, %1, %2, %3;" : "=l"(d) : "l"(a), "l"(b), "l"(c));
    return d;
}
__device__ __forceinline__ ull pack2(float lo, float hi) {
    ull d; unsigned a = __float_as_uint(lo), b = __float_as_uint(hi);
    asm("mov.b64 %0, {%1, %2};" : "=l"(d) : "r"(a), "r"(b));
    return d;
}
__device__ __forceinline__ void unpack2(ull v, float& lo, float& hi) {
    unsigned a, b;
    asm("mov.b64 {%0, %1}, %2;" : "=r"(a), "=r"(b) : "l"(v));
    lo = __uint_as_float(a); hi = __uint_as_float(b);
}

// ================= K1: 16x16 block means (all scales derive from these) =================
__global__ void k_pool(const float* __restrict__ mk, const float* __restrict__ mv) {
    int p = blockIdx.x;
    const float* src; float* dst;
    if (p < 2048) { src = mk + (size_t)p * 9216; dst = g_pool6_k + (size_t)p * 36; }
    else { int q = p - 2048; src = mv + (size_t)q * 9216; dst = g_pool6_v + (size_t)q * 36; }
    __shared__ float rowsum[576];
    int tid = threadIdx.x;
    for (int task = tid; task < 576; task += 256) {
        int r = task / 6, j = task % 6;
        const float4* a = (const float4*)(src + r * 96 + j * 16);
        float4 v0 = a[0], v1 = a[1], v2 = a[2], v3 = a[3];
        rowsum[task] = (v0.x+v0.y+v0.z+v0.w) + (v1.x+v1.y+v1.z+v1.w)
                     + (v2.x+v2.y+v2.z+v2.w) + (v3.x+v3.y+v3.z+v3.w);
    }
    __syncthreads();
    if (tid < 36) {
        int by = tid / 6, bx = tid % 6;
        float s = 0.f;
        #pragma unroll
        for (int k = 0; k < 16; k++) s += rowsum[(by * 16 + k) * 6 + bx];
        dst[tid] = s * (1.0f / 256.0f);
    }
}

// ================= K2: per-(t,b,scale,pos) 1x1 conv + bias + relu =================
__global__ void k_conv(const float* __restrict__ kw, const float* __restrict__ kb,
                       const float* __restrict__ vw, const float* __restrict__ vb) {
    __shared__ float pooled[512];
    int bi = blockIdx.x;
    int kv = bi / 400;
    int rem = bi % 400;
    int tb = rem / 50;          // t*2 + b
    int task = rem % 50;
    int si, pos;
    if (task < 1)       { si = 0; pos = 0; }
    else if (task < 5)  { si = 1; pos = task - 1; }
    else if (task < 14) { si = 2; pos = task - 5; }
    else                { si = 3; pos = task - 14; }
    int s = c_scale[si];
    int g = 6 / s;
    int pi = pos / s, pj = pos % s;
    int C  = kv ? 512 : 256;
    int Co = kv ? 128 : 64;
    const float* p6 = kv ? g_pool6_v : g_pool6_k;
    int tid = threadIdx.x;
    float ginv = 1.0f / (float)(g * g);
    for (int c = tid; c < C; c += 256) {
        const float* pp = p6 + (size_t)(tb * C + c) * 36;
        float sum = 0.f;
        for (int a = 0; a < g; a++)
            for (int bb = 0; bb < g; bb++)
                sum += pp[(pi * g + a) * 6 + (pj * g + bb)];
        pooled[c] = sum * ginv;
    }
    __syncthreads();
    int t = tb >> 1;
    int L = 256 / Co;                 // lanes per output: 4 (keys) / 2 (values)
    int o = tid / L, r = tid % L;
    int chunk = C / L;
    const float* w = (kv ? vw : kw) + (size_t)((t * 4 + si) * Co + o) * C + r * chunk;
    const float* pl = pooled + r * chunk;
    float partial = 0.f;
    for (int i = 0; i < chunk; i += 4) {
        float4 wv = *(const float4*)(w + i);
        float4 pv = *(const float4*)(pl + i);
        partial += wv.x * pv.x + wv.y * pv.y + wv.z * pv.z + wv.w * pv.w;
    }
    for (int off = 1; off < L; off <<= 1)
        partial += __shfl_xor_sync(0xffffffffu, partial, off);
    if (r == 0) {
        float bias = (kv ? vb : kb)[(t * 4 + si) * Co + o];
        float v = fmaxf(partial + bias, 0.0f);
        float* cdst = (kv ? g_convv : g_convk) + (size_t)((tb * 4 + si) * Co + o) * 36 + pos;
        *cdst = v;
    }
}

// ================= K3: bilinear upsample to 6x6 + duplicated attention layouts =================
__global__ void k_upsample() {
    int idx = blockIdx.x * 256 + threadIdx.x;
    if (idx >= 221184) return;
    if (idx < 73728) {
        // keys -> g_mkTd[b][c][2m], fold Ck^-0.5 = 1/16
        int b = idx / (256 * 144);
        int rr = idx % (256 * 144);
        int c = rr / 144, m = rr % 144;
        int t = m / 36, pp = m % 36, i6 = pp / 6, j6 = pp % 6;
        int si = c >> 6, o = c & 63;
        int s = c_scale[si];
        const float* cv = g_convk + (size_t)(((t * 2 + b) * 4 + si) * 64 + o) * 36;
        int yi0 = UI0[si][i6], yi1 = UI1[si][i6]; float wy = UW[si][i6];
        int xi0 = UI0[si][j6], xi1 = UI1[si][j6]; float wx = UW[si][j6];
        float v00 = cv[yi0 * s + xi0], v01 = cv[yi0 * s + xi1];
        float v10 = cv[yi1 * s + xi0], v11 = cv[yi1 * s + xi1];
        float v = (1.f - wy) * ((1.f - wx) * v00 + wx * v01)
                +        wy  * ((1.f - wx) * v10 + wx * v11);
        v *= 0.0625f;
        float* d = g_mkTd + (size_t)(b * 256 + c) * 288 + 2 * m;
        d[0] = v; d[1] = v;
    } else {
        int r0 = idx - 73728;
        int b = r0 / (144 * 512);
        int rr = r0 % (144 * 512);
        int m = rr / 512, vch = rr % 512;
        int t = m / 36, pp = m % 36, i6 = pp / 6, j6 = pp % 6;
        int si = vch >> 7, o = vch & 127;
        int s = c_scale[si];
        const float* cv = g_convv + (size_t)(((t * 2 + b) * 4 + si) * 128 + o) * 36;
        int yi0 = UI0[si][i6], yi1 = UI1[si][i6]; float wy = UW[si][i6];
        int xi0 = UI0[si][j6], xi1 = UI1[si][j6]; float wx = UW[si][j6];
        float v00 = cv[yi0 * s + xi0], v01 = cv[yi0 * s + xi1];
        float v10 = cv[yi1 * s + xi0], v11 = cv[yi1 * s + xi1];
        float v = (1.f - wy) * ((1.f - wx) * v00 + wx * v01)
                +        wy  * ((1.f - wx) * v10 + wx * v11);
        float* d = g_mvTd + (size_t)(b * 144 + m) * 1024 + 2 * vch;
        d[0] = v; d[1] = v;
    }
}

// ================= K4: fused attention (QK -> softmax over M -> AV) + qv copy =================
// grid 144 = 2 b * 72 n-tiles of 128; block 512 threads (16 warps/SM).
// smem (floats): phase1: mkc[32*288]@0, qkc[32*128]@9216      (13312 fl)
//                later : att[144*128]@0, red[16*128]@18432, colmax@20480, colinv@20608,
//                        mvs[18*512]@20736    -> total 29952 floats = 119808 B
__global__ __launch_bounds__(512, 1)
void k_attn(const float* __restrict__ qk, const float* __restrict__ qv,
            float* __restrict__ out) {
    extern __shared__ float sm[];
    float* mkc    = sm;
    float* qkc    = sm + 9216;
    float* att    = sm;
    float* red    = sm + 18432;
    float* colmax = sm + 20480;
    float* colinv = sm + 20608;
    float* mvs    = sm + 20736;

    int tid = threadIdx.x;
    int b = blockIdx.x / 72, ntile = blockIdx.x % 72;
    int n0 = ntile * 128;
    int tm = tid >> 5, tn = tid & 31;       // 16 m-groups (9 m) x 32 n-groups (4 n)

    ull acc[9][2];
    #pragma unroll
    for (int i = 0; i < 9; i++) { acc[i][0] = 0ULL; acc[i][1] = 0ULL; }

    const float* qkb = qk + (size_t)b * 256 * 9216 + n0;
    const float* mkb = g_mkTd + (size_t)b * 256 * 288;

    // ---------- phase 1: scores[m][n] = sum_c mk[c][m]*qk[c][n] ----------
    for (int cc = 0; cc < 8; cc++) {
        __syncthreads();
        {   // mk chunk (duplicated): 32 c x 288 contiguous floats
            const float4* src = (const float4*)(mkb + cc * 32 * 288);
            for (int i = tid; i < 2304; i += 512) ((float4*)mkc)[i] = src[i];
        }
        {   // qk chunk: 32 rows x 128 cols
            for (int i = tid; i < 1024; i += 512) {
                int r = i >> 5, col = i & 31;
                ((float4*)qkc)[r * 32 + col] =
                    ((const float4*)(qkb + (size_t)(cc * 32 + r) * 9216))[col];
            }
        }
        {   // interleaved query_value copy (64 channels per chunk) — hidden under compute
            const float* qvb = qv + (size_t)(b * 512 + cc * 64) * 9216 + n0;
            float* ob = out + (size_t)(b * 1024 + cc * 64) * 9216 + n0;
            for (int i = tid; i < 2048; i += 512) {
                int r = i >> 5, col = i & 31;
                ((float4*)(ob + (size_t)r * 9216))[col] =
                    ((const float4*)(qvb + (size_t)r * 9216))[col];
            }
        }
        __syncthreads();
        #pragma unroll 8
        for (int c = 0; c < 32; c++) {
            const float* krow = mkc + c * 288 + 18 * tm;   // duplicated pairs
            const float* qrow = qkc + c * 128 + 4 * tn;
            ulonglong2 q2 = *(const ulonglong2*)qrow;      // 4 n-cols = 2 f32x2
            ull K[9];
            #pragma unroll
            for (int i = 0; i < 9; i++) K[i] = *(const ull*)(krow + 2 * i);
            #pragma unroll
            for (int i = 0; i < 9; i++) {
                acc[i][0] = fma2(K[i], q2.x, acc[i][0]);
                acc[i][1] = fma2(K[i], q2.y, acc[i][1]);
            }
        }
    }
    __syncthreads();   // done reading mkc/qkc before att overwrites that smem

    // ---------- softmax over m (per column n) ----------
    int nb = 4 * tn;
    #pragma unroll
    for (int j = 0; j < 2; j++) {
        float m0 = -1e30f, m1 = -1e30f;
        #pragma unroll
        for (int i = 0; i < 9; i++) {
            float lo, hi; unpack2(acc[i][j], lo, hi);
            m0 = fmaxf(m0, lo); m1 = fmaxf(m1, hi);
        }
        red[tm * 128 + nb + 2 * j]     = m0;
        red[tm * 128 + nb + 2 * j + 1] = m1;
    }
    __syncthreads();
    if (tid < 128) {
        float m = -1e30f;
        #pragma unroll
        for (int k = 0; k < 16; k++) m = fmaxf(m, red[k * 128 + tid]);
        colmax[tid] = m;
    }
    __syncthreads();
    #pragma unroll
    for (int j = 0; j < 2; j++) {
        float cm0 = colmax[nb + 2 * j], cm1 = colmax[nb + 2 * j + 1];
        float s0 = 0.f, s1 = 0.f;
        #pragma unroll
        for (int i = 0; i < 9; i++) {
            float lo, hi; unpack2(acc[i][j], lo, hi);
            lo = __expf(lo - cm0); hi = __expf(hi - cm1);
            s0 += lo; s1 += hi;
            acc[i][j] = pack2(lo, hi);
        }
        red[tm * 128 + nb + 2 * j]     = s0;
        red[tm * 128 + nb + 2 * j + 1] = s1;
    }
    __syncthreads();
    if (tid < 128) {
        float s = 0.f;
        #pragma unroll
        for (int k = 0; k < 16; k++) s += red[k * 128 + tid];
        colinv[tid] = 1.0f / s;
    }
    __syncthreads();
    #pragma unroll
    for (int j = 0; j < 2; j++) {
        float in0 = colinv[nb + 2 * j], in1 = colinv[nb + 2 * j + 1];
        #pragma unroll
        for (int i = 0; i < 9; i++) {
            float lo, hi; unpack2(acc[i][j], lo, hi);
            int m = 9 * tm + i;
            *(float2*)&att[m * 128 + nb + 2 * j] = make_float2(lo * in0, hi * in1);
        }
    }
    __syncthreads();

    // ---------- phase 2: mem[v][n] = sum_m mv[v][m]*att[m][n] ----------
    int tv = tid >> 4, tn2 = tid & 15;      // 32 v-groups (8 v) x 16 n-groups (8 n)
    const float* mvb = g_mvTd + (size_t)b * 144 * 1024;
    for (int vh = 0; vh < 2; vh++) {
        ull acc2[8][4];
        #pragma unroll
        for (int i = 0; i < 8; i++)
            #pragma unroll
            for (int j = 0; j < 4; j++) acc2[i][j] = 0ULL;
        for (int mc = 0; mc < 8; mc++) {
            __syncthreads();
            // mv chunk (duplicated): 18 m rows x 512 floats (v half vh)
            for (int i = tid; i < 2304; i += 512) {
                int r = i >> 7, col = i & 127;
                ((float4*)mvs)[r * 128 + col] =
                    ((const float4*)(mvb + (size_t)(mc * 18 + r) * 1024 + vh * 512))[col];
            }
            __syncthreads();
            #pragma unroll 6
            for (int m = 0; m < 18; m++) {
                const float* arow = att + (mc * 18 + m) * 128 + 8 * tn2;
                ulonglong2 a01 = ((const ulonglong2*)arow)[0];
                ulonglong2 a23 = ((const ulonglong2*)arow)[1];
                const float* mrow = mvs + m * 512 + 16 * tv;   // duplicated pairs
                ull MV[8];
                #pragma unroll
                for (int i = 0; i < 8; i++) MV[i] = *(const ull*)(mrow + 2 * i);
                #pragma unroll
                for (int i = 0; i < 8; i++) {
                    acc2[i][0] = fma2(MV[i], a01.x, acc2[i][0]);
                    acc2[i][1] = fma2(MV[i], a01.y, acc2[i][1]);
                    acc2[i][2] = fma2(MV[i], a23.x, acc2[i][2]);
                    acc2[i][3] = fma2(MV[i], a23.y, acc2[i][3]);
                }
            }
        }
        float* ob = out + (size_t)(b * 1024 + 512 + vh * 256 + tv * 8) * 9216 + n0 + 8 * tn2;
        #pragma unroll
        for (int i = 0; i < 8; i++) {
            ulonglong2* dst = (ulonglong2*)(ob + (size_t)i * 9216);
            dst[0] = make_ulonglong2(acc2[i][0], acc2[i][1]);
            dst[1] = make_ulonglong2(acc2[i][2], acc2[i][3]);
        }
    }
}

// ================= launch =================
extern "C" void kernel_launch(void* const* d_in, const int* in_sizes, int n_in,
                              void* d_out, int out_size) {
    const float* mk = (const float*)d_in[0];
    const float* mv = (const float*)d_in[1];
    const float* qk = (const float*)d_in[2];
    const float* qv = (const float*)d_in[3];
    const float* kw = (const float*)d_in[4];
    const float* kb = (const float*)d_in[5];
    const float* vw = (const float*)d_in[6];
    const float* vb = (const float*)d_in[7];
    float* out = (float*)d_out;

    k_pool<<<6144, 256>>>(mk, mv);
    k_conv<<<800, 256>>>(kw, kb, vw, vb);
    k_upsample<<<864, 256>>>();
    cudaFuncSetAttribute(k_attn, cudaFuncAttributeMaxDynamicSharedMemorySize, 119808);
    k_attn<<<144, 512, 119808>>>(qk, qv, out);
}

// round 9
// speedup vs baseline: 1.5392x; 1.5392x over previous
#include <cuda_runtime.h>
#include <cuda_bf16.h>
#include <cstdint>

// ---------------- problem constants ----------------
// T=4, B=2, Ck=256, Cv=512, H=W=96, scales {1,2,3,6}, MAX=6, M=144, N=9216

// ---------------- device scratch (static, no allocation) ----------------
__device__ __align__(16) float g_pool6_k[2048 * 36];          // [T*B*Ck][36] block means
__device__ __align__(16) float g_pool6_v[4096 * 36];          // [T*B*Cv][36]
__device__ __align__(16) float g_convk[4 * 2 * 4 * 64 * 36];  // [tb][si][o][pos<=36]
__device__ __align__(16) float g_convv[4 * 2 * 4 * 128 * 36];
// bf16 split operands for tensor-core attention
__device__ __align__(16) __nv_bfloat16 g_mkh[2 * 144 * 256];  // [b][m][c] hi (x Ck^-0.5)
__device__ __align__(16) __nv_bfloat16 g_mkl[2 * 144 * 256];  // lo
__device__ __align__(16) __nv_bfloat16 g_mvh[2 * 512 * 144];  // [b][v][m] hi
__device__ __align__(16) __nv_bfloat16 g_mvl[2 * 512 * 144];  // lo

__constant__ int c_scale[4] = {1, 2, 3, 6};
// bilinear upsample tables (jax.image.resize bilinear, half-pixel == edge clamp here)
__constant__ int UI0[4][6] = {
    {0,0,0,0,0,0},
    {0,0,0,0,1,1},
    {0,0,0,1,1,2},
    {0,1,2,3,4,5}};
__constant__ int UI1[4][6] = {
    {0,0,0,0,0,0},
    {0,1,1,1,1,1},
    {0,1,1,2,2,2},
    {0,1,2,3,4,5}};
__constant__ float UW[4][6] = {
    {0.f,0.f,0.f,0.f,0.f,0.f},
    {0.f, 1.f/6.f, 0.5f, 5.f/6.f, 0.f, 0.f},
    {0.f, 0.25f, 0.75f, 0.25f, 0.75f, 0.f},
    {0.f,0.f,0.f,0.f,0.f,0.f}};

// ---------------- mma helper ----------------
__device__ __forceinline__ void mma_bf16(float* d, const unsigned* a, const unsigned* b) {
    asm volatile(
        "mma.sync.aligned.m16n8k16.row.col.f32.bf16.bf16.f32 "
        "{%0,%1,%2,%3}, {%4,%5,%6,%7}, {%8,%9}, {%0,%1,%2,%3};"
        : "+f"(d[0]), "+f"(d[1]), "+f"(d[2]), "+f"(d[3])
        : "r"(a[0]), "r"(a[1]), "r"(a[2]), "r"(a[3]), "r"(b[0]), "r"(b[1]));
}

__device__ __forceinline__ void split_bf16(float x, __nv_bfloat16& hi, __nv_bfloat16& lo) {
    hi = __float2bfloat16(x);
    lo = __float2bfloat16(x - __bfloat162float(hi));
}

// ================= K1: 16x16 block means + qv passthrough copy =================
__global__ void k_pool(const float* __restrict__ mk, const float* __restrict__ mv,
                       const float* __restrict__ qv, float* __restrict__ out) {
    int p = blockIdx.x;
    int tid = threadIdx.x;
    if (p >= 6144) {
        // qv copy: out[b][0..511][n] = qv[b][ch][n]; 2304 blocks x 4096 floats
        int p2 = p - 6144;
        const float4* src = (const float4*)qv;
        float4* dst = (float4*)out;
        #pragma unroll
        for (int k = 0; k < 4; k++) {
            size_t f4 = (size_t)p2 * 1024 + tid + k * 256;
            size_t b = f4 / (512 * 2304);
            dst[f4 + b * 512 * 2304] = src[f4];
        }
        return;
    }
    const float* src; float* dst;
    if (p < 2048) { src = mk + (size_t)p * 9216; dst = g_pool6_k + (size_t)p * 36; }
    else { int q = p - 2048; src = mv + (size_t)q * 9216; dst = g_pool6_v + (size_t)q * 36; }
    __shared__ float rowsum[576];
    for (int task = tid; task < 576; task += 256) {
        int r = task / 6, j = task % 6;
        const float4* a = (const float4*)(src + r * 96 + j * 16);
        float4 v0 = a[0], v1 = a[1], v2 = a[2], v3 = a[3];
        rowsum[task] = (v0.x+v0.y+v0.z+v0.w) + (v1.x+v1.y+v1.z+v1.w)
                     + (v2.x+v2.y+v2.z+v2.w) + (v3.x+v3.y+v3.z+v3.w);
    }
    __syncthreads();
    if (tid < 36) {
        int by = tid / 6, bx = tid % 6;
        float s = 0.f;
        #pragma unroll
        for (int k = 0; k < 16; k++) s += rowsum[(by * 16 + k) * 6 + bx];
        dst[tid] = s * (1.0f / 256.0f);
    }
}

// ================= K2: per-(t,b,scale,pos) 1x1 conv + bias + relu =================
__global__ void k_conv(const float* __restrict__ kw, const float* __restrict__ kb,
                       const float* __restrict__ vw, const float* __restrict__ vb) {
    __shared__ float pooled[512];
    int bi = blockIdx.x;
    int kv = bi / 400;
    int rem = bi % 400;
    int tb = rem / 50;          // t*2 + b
    int task = rem % 50;
    int si, pos;
    if (task < 1)       { si = 0; pos = 0; }
    else if (task < 5)  { si = 1; pos = task - 1; }
    else if (task < 14) { si = 2; pos = task - 5; }
    else                { si = 3; pos = task - 14; }
    int s = c_scale[si];
    int g = 6 / s;
    int pi = pos / s, pj = pos % s;
    int C  = kv ? 512 : 256;
    int Co = kv ? 128 : 64;
    const float* p6 = kv ? g_pool6_v : g_pool6_k;
    int tid = threadIdx.x;
    float ginv = 1.0f / (float)(g * g);
    for (int c = tid; c < C; c += 256) {
        const float* pp = p6 + (size_t)(tb * C + c) * 36;
        float sum = 0.f;
        for (int a = 0; a < g; a++)
            for (int bb = 0; bb < g; bb++)
                sum += pp[(pi * g + a) * 6 + (pj * g + bb)];
        pooled[c] = sum * ginv;
    }
    __syncthreads();
    int t = tb >> 1;
    int L = 256 / Co;                 // lanes per output: 4 (keys) / 2 (values)
    int o = tid / L, r = tid % L;
    int chunk = C / L;
    const float* w = (kv ? vw : kw) + (size_t)((t * 4 + si) * Co + o) * C + r * chunk;
    const float* pl = pooled + r * chunk;
    float partial = 0.f;
    for (int i = 0; i < chunk; i += 4) {
        float4 wv = *(const float4*)(w + i);
        float4 pv = *(const float4*)(pl + i);
        partial += wv.x * pv.x + wv.y * pv.y + wv.z * pv.z + wv.w * pv.w;
    }
    for (int off = 1; off < L; off <<= 1)
        partial += __shfl_xor_sync(0xffffffffu, partial, off);
    if (r == 0) {
        float bias = (kv ? vb : kb)[(t * 4 + si) * Co + o];
        float v = fmaxf(partial + bias, 0.0f);
        float* cdst = (kv ? g_convv : g_convk) + (size_t)((tb * 4 + si) * Co + o) * 36 + pos;
        *cdst = v;
    }
}

// ================= K3: bilinear upsample to 6x6 + bf16 hi/lo operand layouts =================
__global__ void k_upsample() {
    int idx = blockIdx.x * 256 + threadIdx.x;
    if (idx >= 221184) return;
    if (idx < 73728) {
        // keys -> g_mkh/l[b][m][c], fold Ck^-0.5 = 1/16
        int b = idx / (256 * 144);
        int rr = idx % (256 * 144);
        int c = rr / 144, m = rr % 144;
        int t = m / 36, pp = m % 36, i6 = pp / 6, j6 = pp % 6;
        int si = c >> 6, o = c & 63;
        int s = c_scale[si];
        const float* cv = g_convk + (size_t)(((t * 2 + b) * 4 + si) * 64 + o) * 36;
        int yi0 = UI0[si][i6], yi1 = UI1[si][i6]; float wy = UW[si][i6];
        int xi0 = UI0[si][j6], xi1 = UI1[si][j6]; float wx = UW[si][j6];
        float v00 = cv[yi0 * s + xi0], v01 = cv[yi0 * s + xi1];
        float v10 = cv[yi1 * s + xi0], v11 = cv[yi1 * s + xi1];
        float v = (1.f - wy) * ((1.f - wx) * v00 + wx * v01)
                +        wy  * ((1.f - wx) * v10 + wx * v11);
        v *= 0.0625f;
        __nv_bfloat16 hi, lo;
        split_bf16(v, hi, lo);
        size_t di = (size_t)(b * 144 + m) * 256 + c;
        g_mkh[di] = hi; g_mkl[di] = lo;
    } else {
        int r0 = idx - 73728;
        int b = r0 / (144 * 512);
        int rr = r0 % (144 * 512);
        int m = rr / 512, vch = rr % 512;
        int t = m / 36, pp = m % 36, i6 = pp / 6, j6 = pp % 6;
        int si = vch >> 7, o = vch & 127;
        int s = c_scale[si];
        const float* cv = g_convv + (size_t)(((t * 2 + b) * 4 + si) * 128 + o) * 36;
        int yi0 = UI0[si][i6], yi1 = UI1[si][i6]; float wy = UW[si][i6];
        int xi0 = UI0[si][j6], xi1 = UI1[si][j6]; float wx = UW[si][j6];
        float v00 = cv[yi0 * s + xi0], v01 = cv[yi0 * s + xi1];
        float v10 = cv[yi1 * s + xi0], v11 = cv[yi1 * s + xi1];
        float v = (1.f - wy) * ((1.f - wx) * v00 + wx * v01)
                +        wy  * ((1.f - wx) * v10 + wx * v11);
        __nv_bfloat16 hi, lo;
        split_bf16(v, hi, lo);
        size_t di = (size_t)(b * 512 + vch) * 144 + m;
        g_mvh[di] = hi; g_mvl[di] = lo;
    }
}

// ================= K4: tensor-core attention (bf16-split, fp32 accumulate) =================
// grid 144 = 2 b * 72 n-tiles of 128; 512 threads = 16 warps.
// QK:  scores[144m x 128n] = mk[m][c] x qk[c][n], warp w owns n-frag w (8 cols), 9 m-frags.
// AV:  computes C'[n][v] = att^T[n][m] x mv^T-as-B, warp w: m-frag (w&7), v-half (w>>3).
//
// smem byte layout (all offsets 256-aligned):
//   AV phase : attT_hi @0      [128n][152 bf16]   38912
//              attT_lo @38912  [128n][152]        38912
//              mvch_hi @77824  [128r][24 bf16]     6144
//              mvch_lo @83968  [128r][24]          6144   total 90112
//   QK phase : mkch_hi @0      [144m][40 bf16]    11520
//              mkch_lo @11520                     11520
//              qkT_hi  @23040  [128n][40 bf16]    10240
//              qkT_lo  @33280                     10240   (overlaps attT; barrier-separated)
__global__ __launch_bounds__(512, 1)
void k_attn(const float* __restrict__ qk, float* __restrict__ out) {
    extern __shared__ char smem[];
    __nv_bfloat16* attT_hi = (__nv_bfloat16*)(smem);
    __nv_bfloat16* attT_lo = (__nv_bfloat16*)(smem + 38912);
    __nv_bfloat16* mvch_hi = (__nv_bfloat16*)(smem + 77824);
    __nv_bfloat16* mvch_lo = (__nv_bfloat16*)(smem + 83968);
    __nv_bfloat16* mkch_hi = (__nv_bfloat16*)(smem);
    __nv_bfloat16* mkch_lo = (__nv_bfloat16*)(smem + 11520);
    __nv_bfloat16* qkT_hi  = (__nv_bfloat16*)(smem + 23040);
    __nv_bfloat16* qkT_lo  = (__nv_bfloat16*)(smem + 33280);

    int tid = threadIdx.x;
    int w = tid >> 5, lane = tid & 31;
    int g = lane >> 2, tq = lane & 3;
    int b = blockIdx.x / 72, ntile = blockIdx.x % 72;
    int n0 = ntile * 128;

    // ---------------- phase 1: QK scores ----------------
    float acc[9][4];
    #pragma unroll
    for (int i = 0; i < 9; i++)
        #pragma unroll
        for (int j = 0; j < 4; j++) acc[i][j] = 0.f;

    const float* qkb = qk + (size_t)b * 256 * 9216 + n0;

    for (int cc = 0; cc < 8; cc++) {
        __syncthreads();
        // stage mk chunk: [144m][32c] hi/lo (gmem bf16, 16B vectors)
        for (int q = tid; q < 1152; q += 512) {
            int hl = q / 576, rem = q % 576;
            int m = rem % 144, part = rem / 144;
            const uint4* src = (const uint4*)((hl ? g_mkl : g_mkh)
                               + ((size_t)(b * 144 + m)) * 256 + cc * 32 + part * 8);
            uint4* dst = (uint4*)((hl ? mkch_lo : mkch_hi) + m * 40 + part * 8);
            *dst = *src;
        }
        // stage qk chunk transposed + split: qkT[n][32c] hi/lo
        #pragma unroll
        for (int i = 0; i < 8; i++) {
            int idx = tid + i * 512;           // 4096 elems
            int c = idx >> 7, n = idx & 127;
            float x = qkb[(size_t)(cc * 32 + c) * 9216 + n];
            __nv_bfloat16 hi, lo;
            split_bf16(x, hi, lo);
            qkT_hi[n * 40 + c] = hi;
            qkT_lo[n * 40 + c] = lo;
        }
        __syncthreads();
        #pragma unroll
        for (int kf = 0; kf < 2; kf++) {
            int kb0 = kf * 16 + 2 * tq;
            unsigned bh[2], bl[2];
            const __nv_bfloat16* brow = qkT_hi + (w * 8 + g) * 40 + kb0;
            bh[0] = *(const unsigned*)(brow);
            bh[1] = *(const unsigned*)(brow + 8);
            const __nv_bfloat16* brol = qkT_lo + (w * 8 + g) * 40 + kb0;
            bl[0] = *(const unsigned*)(brol);
            bl[1] = *(const unsigned*)(brol + 8);
            #pragma unroll
            for (int mf = 0; mf < 9; mf++) {
                const __nv_bfloat16* ah0 = mkch_hi + (mf * 16 + g) * 40 + kb0;
                const __nv_bfloat16* al0 = mkch_lo + (mf * 16 + g) * 40 + kb0;
                unsigned ah[4], al[4];
                ah[0] = *(const unsigned*)(ah0);
                ah[1] = *(const unsigned*)(ah0 + 8 * 40);
                ah[2] = *(const unsigned*)(ah0 + 8);
                ah[3] = *(const unsigned*)(ah0 + 8 * 40 + 8);
                al[0] = *(const unsigned*)(al0);
                al[1] = *(const unsigned*)(al0 + 8 * 40);
                al[2] = *(const unsigned*)(al0 + 8);
                al[3] = *(const unsigned*)(al0 + 8 * 40 + 8);
                mma_bf16(acc[mf], ah, bh);
                mma_bf16(acc[mf], ah, bl);
                mma_bf16(acc[mf], al, bh);
            }
        }
    }
    __syncthreads();   // QK staging reads done before attT overwrites

    // ---------------- softmax over m (cols n = w*8 + 2tq + {0,1}) ----------------
    {
        float mx0 = -1e30f, mx1 = -1e30f;
        #pragma unroll
        for (int mf = 0; mf < 9; mf++) {
            mx0 = fmaxf(mx0, fmaxf(acc[mf][0], acc[mf][2]));
            mx1 = fmaxf(mx1, fmaxf(acc[mf][1], acc[mf][3]));
        }
        #pragma unroll
        for (int off = 4; off <= 16; off <<= 1) {
            mx0 = fmaxf(mx0, __shfl_xor_sync(0xffffffffu, mx0, off));
            mx1 = fmaxf(mx1, __shfl_xor_sync(0xffffffffu, mx1, off));
        }
        float s0 = 0.f, s1 = 0.f;
        #pragma unroll
        for (int mf = 0; mf < 9; mf++) {
            acc[mf][0] = __expf(acc[mf][0] - mx0);
            acc[mf][1] = __expf(acc[mf][1] - mx1);
            acc[mf][2] = __expf(acc[mf][2] - mx0);
            acc[mf][3] = __expf(acc[mf][3] - mx1);
            s0 += acc[mf][0] + acc[mf][2];
            s1 += acc[mf][1] + acc[mf][3];
        }
        #pragma unroll
        for (int off = 4; off <= 16; off <<= 1) {
            s0 += __shfl_xor_sync(0xffffffffu, s0, off);
            s1 += __shfl_xor_sync(0xffffffffu, s1, off);
        }
        float in0 = 1.0f / s0, in1 = 1.0f / s1;
        int ncol0 = w * 8 + 2 * tq, ncol1 = ncol0 + 1;
        #pragma unroll
        for (int mf = 0; mf < 9; mf++) {
            int m0 = mf * 16 + g, m1 = m0 + 8;
            __nv_bfloat16 hi, lo;
            split_bf16(acc[mf][0] * in0, hi, lo);
            attT_hi[ncol0 * 152 + m0] = hi; attT_lo[ncol0 * 152 + m0] = lo;
            split_bf16(acc[mf][1] * in1, hi, lo);
            attT_hi[ncol1 * 152 + m0] = hi; attT_lo[ncol1 * 152 + m0] = lo;
            split_bf16(acc[mf][2] * in0, hi, lo);
            attT_hi[ncol0 * 152 + m1] = hi; attT_lo[ncol0 * 152 + m1] = lo;
            split_bf16(acc[mf][3] * in1, hi, lo);
            attT_hi[ncol1 * 152 + m1] = hi; attT_lo[ncol1 * 152 + m1] = lo;
        }
    }

    // ---------------- phase 2: AV  (C'[n][v], warp: m-frag w&7, v-half w>>3) ----------------
    int mfa = w & 7;
    int vhalf = w >> 3;
    for (int p = 0; p < 4; p++) {
        float acc2[8][4];
        #pragma unroll
        for (int j = 0; j < 8; j++)
            #pragma unroll
            for (int q = 0; q < 4; q++) acc2[j][q] = 0.f;
        for (int kf = 0; kf < 9; kf++) {
            __syncthreads();
            {   // stage mv chunk: rows r 0..127 -> v = (r>>6)*256 + p*64 + (r&63), cols kf*16..+15
                int hl = tid & 1, part = (tid >> 1) & 1, r = tid >> 2;
                int v = ((r >> 6) << 8) + p * 64 + (r & 63);
                const uint4* src = (const uint4*)((hl ? g_mvl : g_mvh)
                                   + ((size_t)(b * 512 + v)) * 144 + kf * 16 + part * 8);
                uint4* dst = (uint4*)((hl ? mvch_lo : mvch_hi) + r * 24 + part * 8);
                *dst = *src;
            }
            __syncthreads();
            int kb0 = kf * 16 + 2 * tq;
            const __nv_bfloat16* ah0 = attT_hi + (mfa * 16 + g) * 152 + kb0;
            const __nv_bfloat16* al0 = attT_lo + (mfa * 16 + g) * 152 + kb0;
            unsigned ah[4], al[4];
            ah[0] = *(const unsigned*)(ah0);
            ah[1] = *(const unsigned*)(ah0 + 8 * 152);
            ah[2] = *(const unsigned*)(ah0 + 8);
            ah[3] = *(const unsigned*)(ah0 + 8 * 152 + 8);
            al[0] = *(const unsigned*)(al0);
            al[1] = *(const unsigned*)(al0 + 8 * 152);
            al[2] = *(const unsigned*)(al0 + 8);
            al[3] = *(const unsigned*)(al0 + 8 * 152 + 8);
            #pragma unroll
            for (int j = 0; j < 8; j++) {
                int r = vhalf * 64 + j * 8 + g;
                unsigned bh[2], bl[2];
                const __nv_bfloat16* brow = mvch_hi + r * 24 + 2 * tq;
                bh[0] = *(const unsigned*)(brow);
                bh[1] = *(const unsigned*)(brow + 8);
                const __nv_bfloat16* brol = mvch_lo + r * 24 + 2 * tq;
                bl[0] = *(const unsigned*)(brol);
                bl[1] = *(const unsigned*)(brol + 8);
                mma_bf16(acc2[j], ah, bh);
                mma_bf16(acc2[j], ah, bl);
                mma_bf16(acc2[j], al, bh);
            }
        }
        // epilogue: C'[n][v]: rows n = 16*mfa + g (+8), cols v = vbase + 2tq (+1)
        #pragma unroll
        for (int j = 0; j < 8; j++) {
            int v = vhalf * 256 + p * 64 + j * 8 + 2 * tq;
            float* p0 = out + (size_t)(b * 1024 + 512 + v) * 9216 + n0 + 16 * mfa + g;
            p0[0]        = acc2[j][0];
            p0[8]        = acc2[j][2];
            p0[9216]     = acc2[j][1];
            p0[9216 + 8] = acc2[j][3];
        }
    }
}

// ================= launch =================
extern "C" void kernel_launch(void* const* d_in, const int* in_sizes, int n_in,
                              void* d_out, int out_size) {
    const float* mk = (const float*)d_in[0];
    const float* mv = (const float*)d_in[1];
    const float* qk = (const float*)d_in[2];
    const float* qv = (const float*)d_in[3];
    const float* kw = (const float*)d_in[4];
    const float* kb = (const float*)d_in[5];
    const float* vw = (const float*)d_in[6];
    const float* vb = (const float*)d_in[7];
    float* out = (float*)d_out;

    k_pool<<<8448, 256>>>(mk, mv, qv, out);
    k_conv<<<800, 256>>>(kw, kb, vw, vb);
    k_upsample<<<864, 256>>>();
    cudaFuncSetAttribute(k_attn, cudaFuncAttributeMaxDynamicSharedMemorySize, 90112);
    k_attn<<<144, 512, 90112>>>(qk, out);
}